// round 6
// baseline (speedup 1.0000x reference)
#include <cuda_runtime.h>
#include <cuda_fp16.h>
#include <cuda_bf16.h>
#include <cstdint>

#define NN 16384
#define KK 1024
#define DD 512
#define ITERS 20
#define HSCALE 16.0f
#define INV_HSCALE (1.0f/16.0f)
#define MU_F (1.0f/16384.0f)
#define NU_F (1.0f/1024.0f)

// ---------------- scratch (static device globals; no runtime allocation) ----------------
__device__ float  g_C[(size_t)NN * KK];     // raw cost matrix (64 MB)
__device__ __half g_Kh[(size_t)NN * KK];    // K_eps * 16 in fp16 (32 MB)
__device__ __nv_bfloat16 g_xh[(size_t)NN * DD];
__device__ __nv_bfloat16 g_xl[(size_t)NN * DD];
__device__ __nv_bfloat16 g_ph[(size_t)KK * DD];
__device__ __nv_bfloat16 g_pl[(size_t)KK * DD];
__device__ float  g_u[NN];
__device__ float  g_v[KK];
__device__ float  g_s[KK];
__device__ float  g_dx[NN];
__device__ float  g_dp[KK];
__device__ int    g_cmax_bits;

__device__ __forceinline__ float2 h2f2(unsigned v) {
    __half2 h = *reinterpret_cast<__half2*>(&v);
    return __half22float2(h);
}

__device__ __forceinline__ uint32_t s2u(const void* p) {
    uint32_t r;
    asm("{ .reg .u64 t; cvta.to.shared.u64 t, %1; cvt.u32.u64 %0, t; }" : "=r"(r) : "l"(p));
    return r;
}
__device__ __forceinline__ void cp16u(uint32_t dst, const void* src) {
    asm volatile("cp.async.cg.shared.global [%0], [%1], 16;" :: "r"(dst), "l"(src));
}
__device__ __forceinline__ void ldsm4(unsigned* r, uint32_t a) {
    asm volatile("ldmatrix.sync.aligned.m8n8.x4.shared.b16 {%0,%1,%2,%3}, [%4];"
        : "=r"(r[0]), "=r"(r[1]), "=r"(r[2]), "=r"(r[3]) : "r"(a));
}
__device__ __forceinline__ void mma_bf16_2(float* d, const unsigned* a,
                                           unsigned b0, unsigned b1) {
    asm volatile(
        "mma.sync.aligned.m16n8k16.row.col.f32.bf16.bf16.f32 "
        "{%0,%1,%2,%3}, {%4,%5,%6,%7}, {%8,%9}, {%0,%1,%2,%3};"
        : "+f"(d[0]), "+f"(d[1]), "+f"(d[2]), "+f"(d[3])
        : "r"(a[0]), "r"(a[1]), "r"(a[2]), "r"(a[3]), "r"(b0), "r"(b1));
}

// ---------------- init ----------------
__global__ void init_kernel(float* __restrict__ out) {
    int t = blockIdx.x * 256 + threadIdx.x;
    if (t < KK) { g_v[t] = 1.0f; g_s[t] = 0.0f; }
    if (t == 0) { g_cmax_bits = 0; out[(size_t)NN * KK] = 0.0f; }
}

// ---------------- split f32 -> bf16 hi/lo + row squared norm ----------------
__global__ void split_kernel(const float* __restrict__ src, int which) {
    int row = blockIdx.x;
    int t = threadIdx.x;  // 128 threads, 4 floats each
    float4 v = reinterpret_cast<const float4*>(src + (size_t)row * DD)[t];

    __nv_bfloat16 h[4], l[4];
    float vv[4] = {v.x, v.y, v.z, v.w};
#pragma unroll
    for (int i = 0; i < 4; i++) {
        h[i] = __float2bfloat16(vv[i]);
        l[i] = __float2bfloat16(vv[i] - __bfloat162float(h[i]));
    }
    __nv_bfloat16* dh = which ? g_ph : g_xh;
    __nv_bfloat16* dl = which ? g_pl : g_xl;
    size_t off = (size_t)row * DD + t * 4;
    *reinterpret_cast<uint2*>(dh + off) = *reinterpret_cast<uint2*>(h);
    *reinterpret_cast<uint2*>(dl + off) = *reinterpret_cast<uint2*>(l);

    float nrm = v.x * v.x + v.y * v.y + v.z * v.z + v.w * v.w;
#pragma unroll
    for (int o = 16; o; o >>= 1) nrm += __shfl_xor_sync(0xffffffffu, nrm, o);
    __shared__ float w[4];
    int lane = t & 31, wid = t >> 5;
    if (!lane) w[wid] = nrm;
    __syncthreads();
    if (t == 0) {
        float s = w[0] + w[1] + w[2] + w[3];
        if (which == 0) g_dx[row] = s; else g_dp[row] = s;
    }
}

// ---------------- HMMA GEMM + cost epilogue ----------------
// CTA tile 128(M) x 128(N over KK), BK=64, double-buffered cp.async, ldmatrix frags.
// 8 warps: warpM = wid&3 (32 rows), warpN = wid>>2 (64 cols).
// bf16 2-term split: G = xh*ph + xh*pl + xl*ph, fp32 accum.
// MMA passes issued pass-outermost so each accumulator is touched once per 16 MMAs.
#define BK 64
#define NCHUNK (DD / BK)          // 8
#define ROWB 144                  // bytes per 64-element bf16 row (128 + 16 pad)
#define PARTB (128 * ROWB)        // 18432
#define STAGEB (4 * PARTB)        // 73728: [Ah, Al, Bh, Bl]
#define GEMM_SMEM (2 * STAGEB)    // 147456

__device__ __forceinline__ void load_chunk(uint32_t st, int bm, int bn, int k0, int tid) {
#pragma unroll
    for (int part = 0; part < 4; part++) {
        const __nv_bfloat16* src =
            (part == 0) ? g_xh : (part == 1) ? g_xl : (part == 2) ? g_ph : g_pl;
        const int rbase = (part < 2) ? bm : bn;
        uint32_t dst = st + part * PARTB;
#pragma unroll
        for (int i = 0; i < 4; i++) {
            int g = tid + i * 256;          // 1024 granules of 16B per part
            int row = g >> 3, c = g & 7;
            cp16u(dst + row * ROWB + c * 16,
                  src + (size_t)(rbase + row) * DD + k0 + c * 8);
        }
    }
}

__global__ __launch_bounds__(256, 1)
void gemm_mma_kernel() {
    extern __shared__ __align__(16) char smem[];
    __shared__ float dpc[128];
    const uint32_t sb = s2u(smem);
    const int tid = threadIdx.x;
    const int wid = tid >> 5, lane = tid & 31;
    const int g = lane >> 2;          // group id 0..7
    const int t2 = (lane & 3) * 2;    // k-pair offset
    const int warpM = wid & 3, warpN = wid >> 2;
    const int bn = blockIdx.x * 128;  // over KK
    const int bm = blockIdx.y * 128;  // over NN

    if (tid < 128) dpc[tid] = g_dp[bn + tid];

    const uint32_t aoff = (uint32_t)((warpM * 32 + (lane & 15)) * ROWB + (lane >> 4) * 16);
    const uint32_t boff = (uint32_t)((warpN * 64 + (lane & 15)) * ROWB + (lane >> 4) * 16);

    float d[2][8][4];
#pragma unroll
    for (int mi = 0; mi < 2; mi++)
#pragma unroll
        for (int ni = 0; ni < 8; ni++)
#pragma unroll
            for (int q = 0; q < 4; q++) d[mi][ni][q] = 0.0f;

    load_chunk(sb, bm, bn, 0, tid);
    asm volatile("cp.async.commit_group;");

    for (int s = 0; s < NCHUNK; s++) {
        if (s + 1 < NCHUNK) {
            load_chunk(sb + ((s + 1) & 1) * STAGEB, bm, bn, (s + 1) * BK, tid);
            asm volatile("cp.async.commit_group;");
            asm volatile("cp.async.wait_group 1;");
        } else {
            asm volatile("cp.async.wait_group 0;");
        }
        __syncthreads();

        const uint32_t Ah = sb + (s & 1) * STAGEB;
        const uint32_t Al = Ah + PARTB;
        const uint32_t Bh = Ah + 2 * PARTB;
        const uint32_t Bl = Ah + 3 * PARTB;

#pragma unroll
        for (int ks = 0; ks < 4; ks++) {       // 4 x k16 per chunk
            unsigned ah[2][4], al[2][4], bh[4][4], bl[4][4];
            ldsm4(ah[0], Ah + aoff + ks * 32);
            ldsm4(ah[1], Ah + aoff + 16 * ROWB + ks * 32);
            ldsm4(al[0], Al + aoff + ks * 32);
            ldsm4(al[1], Al + aoff + 16 * ROWB + ks * 32);
#pragma unroll
            for (int q = 0; q < 4; q++) {
                ldsm4(bh[q], Bh + boff + q * 16 * ROWB + ks * 32);
                ldsm4(bl[q], Bl + boff + q * 16 * ROWB + ks * 32);
            }
            // pass 1: ah * bh  (16 MMAs, all accumulators distinct)
#pragma unroll
            for (int q = 0; q < 4; q++)
#pragma unroll
                for (int mi = 0; mi < 2; mi++) {
                    mma_bf16_2(d[mi][2 * q],     ah[mi], bh[q][0], bh[q][2]);
                    mma_bf16_2(d[mi][2 * q + 1], ah[mi], bh[q][1], bh[q][3]);
                }
            // pass 2: ah * bl
#pragma unroll
            for (int q = 0; q < 4; q++)
#pragma unroll
                for (int mi = 0; mi < 2; mi++) {
                    mma_bf16_2(d[mi][2 * q],     ah[mi], bl[q][0], bl[q][2]);
                    mma_bf16_2(d[mi][2 * q + 1], ah[mi], bl[q][1], bl[q][3]);
                }
            // pass 3: al * bh
#pragma unroll
            for (int q = 0; q < 4; q++)
#pragma unroll
                for (int mi = 0; mi < 2; mi++) {
                    mma_bf16_2(d[mi][2 * q],     al[mi], bh[q][0], bh[q][2]);
                    mma_bf16_2(d[mi][2 * q + 1], al[mi], bh[q][1], bh[q][3]);
                }
        }
        __syncthreads();
    }

    // epilogue: C = dx + dp - 2*G, track max
    float tmax = 0.0f;
#pragma unroll
    for (int mi = 0; mi < 2; mi++) {
#pragma unroll
        for (int h = 0; h < 2; h++) {
            int row = bm + warpM * 32 + mi * 16 + h * 8 + g;
            float dxr = g_dx[row];
            float* cp = g_C + (size_t)row * KK + bn + warpN * 64;
#pragma unroll
            for (int ni = 0; ni < 8; ni++) {
                int c0 = ni * 8 + t2;
                float o0 = dxr + dpc[warpN * 64 + c0]     - 2.0f * d[mi][ni][h * 2];
                float o1 = dxr + dpc[warpN * 64 + c0 + 1] - 2.0f * d[mi][ni][h * 2 + 1];
                tmax = fmaxf(tmax, fmaxf(o0, o1));
                *reinterpret_cast<float2*>(cp + c0) = make_float2(o0, o1);
            }
        }
    }
#pragma unroll
    for (int o = 16; o; o >>= 1)
        tmax = fmaxf(tmax, __shfl_xor_sync(0xffffffffu, tmax, o));
    if (!lane) atomicMax(&g_cmax_bits, __float_as_int(tmax));
}

// ---------------- K_eps (fp16, x16 scaled): Kh = 16 * exp(-C / ((max+1e-8)*0.1)) ----------------
__global__ void expk_kernel() {
    float negK = -10.0f / (__int_as_float(g_cmax_bits) + 1e-8f);
    size_t nvec = (size_t)NN * KK / 4;
    size_t stride = (size_t)gridDim.x * blockDim.x;
    for (size_t t = (size_t)blockIdx.x * blockDim.x + threadIdx.x; t < nvec; t += stride) {
        float4 c = *reinterpret_cast<const float4*>(g_C + t * 4);
        __half2 h0 = __floats2half2_rn(__expf(c.x * negK) * HSCALE,
                                       __expf(c.y * negK) * HSCALE);
        __half2 h1 = __floats2half2_rn(__expf(c.z * negK) * HSCALE,
                                       __expf(c.w * negK) * HSCALE);
        uint2 pk;
        pk.x = *reinterpret_cast<unsigned*>(&h0);
        pk.y = *reinterpret_cast<unsigned*>(&h1);
        *reinterpret_cast<uint2*>(g_Kh + t * 4) = pk;
    }
}

// ---------------- fused u-step + column-sum: one pass over Kh per iteration ----------------
#define RPW 4
#define ROWS_PER_BLOCK (8 * RPW)   // 32 -> 512 blocks
__global__ __launch_bounds__(256)
void fused_uv_kernel() {
    const int tid = threadIdx.x;
    const int lane = tid & 31;
    const int wid  = tid >> 5;
    const int rowbase = blockIdx.x * ROWS_PER_BLOCK + wid * RPW;

    float vr[32];
#pragma unroll
    for (int q = 0; q < 4; q++) {
        int e = (lane + 32 * q) * 8;
        float4 a = *reinterpret_cast<const float4*>(g_v + e);
        float4 b = *reinterpret_cast<const float4*>(g_v + e + 4);
        vr[q * 8 + 0] = a.x; vr[q * 8 + 1] = a.y; vr[q * 8 + 2] = a.z; vr[q * 8 + 3] = a.w;
        vr[q * 8 + 4] = b.x; vr[q * 8 + 5] = b.y; vr[q * 8 + 6] = b.z; vr[q * 8 + 7] = b.w;
    }
    float colacc[32];
#pragma unroll
    for (int j = 0; j < 32; j++) colacc[j] = 0.0f;

    for (int r = 0; r < RPW; r++) {
        const int row = rowbase + r;
        const __half* rp = g_Kh + (size_t)row * KK;
        float kh[32];
#pragma unroll
        for (int q = 0; q < 4; q++) {
            int e = (lane + 32 * q) * 8;
            int4 raw = *reinterpret_cast<const int4*>(rp + e);
            float2 f;
            f = h2f2((unsigned)raw.x); kh[q * 8 + 0] = f.x; kh[q * 8 + 1] = f.y;
            f = h2f2((unsigned)raw.y); kh[q * 8 + 2] = f.x; kh[q * 8 + 3] = f.y;
            f = h2f2((unsigned)raw.z); kh[q * 8 + 4] = f.x; kh[q * 8 + 5] = f.y;
            f = h2f2((unsigned)raw.w); kh[q * 8 + 6] = f.x; kh[q * 8 + 7] = f.y;
        }
        float dot = 0.0f;
#pragma unroll
        for (int j = 0; j < 32; j++) dot = fmaf(kh[j], vr[j], dot);
#pragma unroll
        for (int o = 16; o; o >>= 1) dot += __shfl_xor_sync(0xffffffffu, dot, o);
        float u = MU_F / (dot * INV_HSCALE + 1e-8f);
        if (!lane) g_u[row] = u;
#pragma unroll
        for (int j = 0; j < 32; j++) colacc[j] = fmaf(u, kh[j], colacc[j]);
    }

    __shared__ float sm[8][KK];
#pragma unroll
    for (int q = 0; q < 4; q++) {
        int e = (lane + 32 * q) * 8;
        *reinterpret_cast<float4*>(&sm[wid][e]) =
            make_float4(colacc[q * 8 + 0], colacc[q * 8 + 1], colacc[q * 8 + 2], colacc[q * 8 + 3]);
        *reinterpret_cast<float4*>(&sm[wid][e + 4]) =
            make_float4(colacc[q * 8 + 4], colacc[q * 8 + 5], colacc[q * 8 + 6], colacc[q * 8 + 7]);
    }
    __syncthreads();
#pragma unroll
    for (int c = 0; c < 4; c++) {
        int col = tid + c * 256;
        float s = sm[0][col];
#pragma unroll
        for (int w = 1; w < 8; w++) s += sm[w][col];
        atomicAdd(&g_s[col], s);
    }
}

// ---------------- v-step: v_j = nu / (s_j / 16 + 1e-8); re-zero s ----------------
__global__ void v_kernel() {
    int j = blockIdx.x * 256 + threadIdx.x;
    if (j < KK) {
        g_v[j] = NU_F / (g_s[j] * INV_HSCALE + 1e-8f);
        g_s[j] = 0.0f;
    }
}

// ---------------- final: T = u * exp(-Cn/eps) * v, loss = sum(T * Cn) ----------------
__global__ __launch_bounds__(256)
void final_kernel(float* __restrict__ out) {
    float invM = 1.0f / (__int_as_float(g_cmax_bits) + 1e-8f);
    size_t nvec = (size_t)NN * KK / 4;
    size_t stride = (size_t)gridDim.x * blockDim.x;
    float lsum = 0.f;
    for (size_t t = (size_t)blockIdx.x * blockDim.x + threadIdx.x; t < nvec; t += stride) {
        size_t base = t * 4;
        int i = (int)(base >> 10);
        int j = (int)(base & 1023);
        float4 c = *reinterpret_cast<const float4*>(g_C + base);
        float4 vj = *reinterpret_cast<const float4*>(g_v + j);
        float ui = g_u[i];
        float cn0 = c.x * invM, cn1 = c.y * invM, cn2 = c.z * invM, cn3 = c.w * invM;
        float t0 = ui * __expf(-cn0 * 10.0f) * vj.x;
        float t1 = ui * __expf(-cn1 * 10.0f) * vj.y;
        float t2 = ui * __expf(-cn2 * 10.0f) * vj.z;
        float t3 = ui * __expf(-cn3 * 10.0f) * vj.w;
        *reinterpret_cast<float4*>(out + base) = make_float4(t0, t1, t2, t3);
        lsum += t0 * cn0 + t1 * cn1 + t2 * cn2 + t3 * cn3;
    }
#pragma unroll
    for (int o = 16; o; o >>= 1) lsum += __shfl_xor_sync(0xffffffffu, lsum, o);
    __shared__ float ws[8];
    int lane = threadIdx.x & 31, wid = threadIdx.x >> 5;
    if (!lane) ws[wid] = lsum;
    __syncthreads();
    if (threadIdx.x == 0) {
        float s = 0.f;
#pragma unroll
        for (int i = 0; i < 8; i++) s += ws[i];
        atomicAdd(out + (size_t)NN * KK, s);
    }
}

// ---------------- launch ----------------
extern "C" void kernel_launch(void* const* d_in, const int* in_sizes, int n_in,
                              void* d_out, int out_size) {
    const float* x = (const float*)d_in[0];   // [16384, 512]
    const float* p = (const float*)d_in[1];   // [1024, 512]
    float* out = (float*)d_out;               // T_star [16384,1024] then loss scalar

    cudaFuncSetAttribute(gemm_mma_kernel,
                         cudaFuncAttributeMaxDynamicSharedMemorySize, GEMM_SMEM);

    init_kernel<<<4, 256>>>(out);
    split_kernel<<<NN, 128>>>(x, 0);
    split_kernel<<<KK, 128>>>(p, 1);
    gemm_mma_kernel<<<dim3(KK / 128, NN / 128), 256, GEMM_SMEM>>>();
    expk_kernel<<<4096, 256>>>();
    for (int it = 0; it < ITERS; it++) {
        fused_uv_kernel<<<NN / ROWS_PER_BLOCK, 256>>>();
        v_kernel<<<4, 256>>>();
    }
    final_kernel<<<2048, 256>>>(out);
}

// round 7
// speedup vs baseline: 1.5246x; 1.5246x over previous
#include <cuda_runtime.h>
#include <cuda_fp16.h>
#include <cstdint>

#define NN 16384
#define KK 1024
#define DD 512
#define ITERS 20
#define HSCALE 16.0f
#define INV_HSCALE (1.0f/16.0f)
#define MU_F (1.0f/16384.0f)
#define NU_F (1.0f/1024.0f)

// ---------------- scratch (static device globals; no runtime allocation) ----------------
__device__ float  g_C[(size_t)NN * KK];     // raw cost matrix (64 MB)
__device__ __half g_Kh[(size_t)NN * KK];    // K_eps * 16 in fp16 (32 MB)
__device__ __half g_xh[(size_t)NN * DD];    // fp16 copy of x
__device__ __half g_ph[(size_t)KK * DD];    // fp16 copy of p
__device__ float  g_u[NN];
__device__ float  g_v[KK];
__device__ float  g_s[KK];
__device__ float  g_dx[NN];
__device__ float  g_dp[KK];
__device__ int    g_cmax_bits;

__device__ __forceinline__ float2 h2f2(unsigned v) {
    __half2 h = *reinterpret_cast<__half2*>(&v);
    return __half22float2(h);
}

__device__ __forceinline__ uint32_t s2u(const void* p) {
    uint32_t r;
    asm("{ .reg .u64 t; cvta.to.shared.u64 t, %1; cvt.u32.u64 %0, t; }" : "=r"(r) : "l"(p));
    return r;
}
__device__ __forceinline__ void cp16u(uint32_t dst, const void* src) {
    asm volatile("cp.async.cg.shared.global [%0], [%1], 16;" :: "r"(dst), "l"(src));
}
__device__ __forceinline__ void ldsm4(unsigned* r, uint32_t a) {
    asm volatile("ldmatrix.sync.aligned.m8n8.x4.shared.b16 {%0,%1,%2,%3}, [%4];"
        : "=r"(r[0]), "=r"(r[1]), "=r"(r[2]), "=r"(r[3]) : "r"(a));
}
__device__ __forceinline__ void mma_f16(float* d, const unsigned* a,
                                        unsigned b0, unsigned b1) {
    asm volatile(
        "mma.sync.aligned.m16n8k16.row.col.f32.f16.f16.f32 "
        "{%0,%1,%2,%3}, {%4,%5,%6,%7}, {%8,%9}, {%0,%1,%2,%3};"
        : "+f"(d[0]), "+f"(d[1]), "+f"(d[2]), "+f"(d[3])
        : "r"(a[0]), "r"(a[1]), "r"(a[2]), "r"(a[3]), "r"(b0), "r"(b1));
}

// ---------------- init ----------------
__global__ void init_kernel(float* __restrict__ out) {
    int t = blockIdx.x * 256 + threadIdx.x;
    if (t < KK) { g_v[t] = 1.0f; g_s[t] = 0.0f; }
    if (t == 0) { g_cmax_bits = 0; out[(size_t)NN * KK] = 0.0f; }
}

// ---------------- convert f32 -> fp16 + row squared norm ----------------
__global__ void split_kernel(const float* __restrict__ src, int which) {
    int row = blockIdx.x;
    int t = threadIdx.x;  // 128 threads, 4 floats each
    float4 v = reinterpret_cast<const float4*>(src + (size_t)row * DD)[t];

    __half2 h0 = __floats2half2_rn(v.x, v.y);
    __half2 h1 = __floats2half2_rn(v.z, v.w);
    __half* dh = which ? g_ph : g_xh;
    uint2 pk;
    pk.x = *reinterpret_cast<unsigned*>(&h0);
    pk.y = *reinterpret_cast<unsigned*>(&h1);
    *reinterpret_cast<uint2*>(dh + (size_t)row * DD + t * 4) = pk;

    float nrm = v.x * v.x + v.y * v.y + v.z * v.z + v.w * v.w;
#pragma unroll
    for (int o = 16; o; o >>= 1) nrm += __shfl_xor_sync(0xffffffffu, nrm, o);
    __shared__ float w[4];
    int lane = t & 31, wid = t >> 5;
    if (!lane) w[wid] = nrm;
    __syncthreads();
    if (t == 0) {
        float s = w[0] + w[1] + w[2] + w[3];
        if (which == 0) g_dx[row] = s; else g_dp[row] = s;
    }
}

// ---------------- HMMA GEMM (single-pass fp16) + cost epilogue ----------------
// CTA tile 128(M) x 128(N over KK), BK=64, double-buffered cp.async, ldmatrix frags.
// 8 warps: warpM = wid&3 (32 rows), warpN = wid>>2 (64 cols). 2 CTAs/SM.
#define BK 64
#define NCHUNK (DD / BK)          // 8
#define ROWB 144                  // bytes per 64-element fp16 row (128 + 16 pad)
#define PARTB (128 * ROWB)        // 18432
#define STAGEB (2 * PARTB)        // 36864: [A, B]
#define GEMM_SMEM (2 * STAGEB)    // 73728

__device__ __forceinline__ void load_chunk(uint32_t st, int bm, int bn, int k0, int tid) {
#pragma unroll
    for (int part = 0; part < 2; part++) {
        const __half* src = part ? g_ph : g_xh;
        const int rbase = part ? bn : bm;
        uint32_t dst = st + part * PARTB;
#pragma unroll
        for (int i = 0; i < 4; i++) {
            int g = tid + i * 256;          // 1024 granules of 16B per part
            int row = g >> 3, c = g & 7;
            cp16u(dst + row * ROWB + c * 16,
                  src + (size_t)(rbase + row) * DD + k0 + c * 8);
        }
    }
}

__global__ __launch_bounds__(256, 2)
void gemm_mma_kernel() {
    extern __shared__ __align__(16) char smem[];
    __shared__ float dpc[128];
    const uint32_t sb = s2u(smem);
    const int tid = threadIdx.x;
    const int wid = tid >> 5, lane = tid & 31;
    const int g = lane >> 2;          // group id 0..7
    const int t2 = (lane & 3) * 2;    // k-pair offset
    const int warpM = wid & 3, warpN = wid >> 2;
    const int bn = blockIdx.x * 128;  // over KK
    const int bm = blockIdx.y * 128;  // over NN

    if (tid < 128) dpc[tid] = g_dp[bn + tid];

    const uint32_t aoff = (uint32_t)((warpM * 32 + (lane & 15)) * ROWB + (lane >> 4) * 16);
    const uint32_t boff = (uint32_t)((warpN * 64 + (lane & 15)) * ROWB + (lane >> 4) * 16);

    float d[2][8][4];
#pragma unroll
    for (int mi = 0; mi < 2; mi++)
#pragma unroll
        for (int ni = 0; ni < 8; ni++)
#pragma unroll
            for (int q = 0; q < 4; q++) d[mi][ni][q] = 0.0f;

    load_chunk(sb, bm, bn, 0, tid);
    asm volatile("cp.async.commit_group;");

    for (int s = 0; s < NCHUNK; s++) {
        if (s + 1 < NCHUNK) {
            load_chunk(sb + ((s + 1) & 1) * STAGEB, bm, bn, (s + 1) * BK, tid);
            asm volatile("cp.async.commit_group;");
            asm volatile("cp.async.wait_group 1;");
        } else {
            asm volatile("cp.async.wait_group 0;");
        }
        __syncthreads();

        const uint32_t A = sb + (s & 1) * STAGEB;
        const uint32_t B = A + PARTB;

#pragma unroll
        for (int ks = 0; ks < 4; ks++) {       // 4 x k16 per chunk
            unsigned a[2][4], b[4][4];
            ldsm4(a[0], A + aoff + ks * 32);
            ldsm4(a[1], A + aoff + 16 * ROWB + ks * 32);
#pragma unroll
            for (int q = 0; q < 4; q++)
                ldsm4(b[q], B + boff + q * 16 * ROWB + ks * 32);
#pragma unroll
            for (int q = 0; q < 4; q++)
#pragma unroll
                for (int mi = 0; mi < 2; mi++) {
                    mma_f16(d[mi][2 * q],     a[mi], b[q][0], b[q][2]);
                    mma_f16(d[mi][2 * q + 1], a[mi], b[q][1], b[q][3]);
                }
        }
        __syncthreads();
    }

    // epilogue: C = dx + dp - 2*G, track max
    float tmax = 0.0f;
#pragma unroll
    for (int mi = 0; mi < 2; mi++) {
#pragma unroll
        for (int h = 0; h < 2; h++) {
            int row = bm + warpM * 32 + mi * 16 + h * 8 + g;
            float dxr = g_dx[row];
            float* cp = g_C + (size_t)row * KK + bn + warpN * 64;
#pragma unroll
            for (int ni = 0; ni < 8; ni++) {
                int c0 = ni * 8 + t2;
                float o0 = dxr + dpc[warpN * 64 + c0]     - 2.0f * d[mi][ni][h * 2];
                float o1 = dxr + dpc[warpN * 64 + c0 + 1] - 2.0f * d[mi][ni][h * 2 + 1];
                tmax = fmaxf(tmax, fmaxf(o0, o1));
                *reinterpret_cast<float2*>(cp + c0) = make_float2(o0, o1);
            }
        }
    }
#pragma unroll
    for (int o = 16; o; o >>= 1)
        tmax = fmaxf(tmax, __shfl_xor_sync(0xffffffffu, tmax, o));
    if (!lane) atomicMax(&g_cmax_bits, __float_as_int(tmax));
}

// ---------------- K_eps (fp16, x16 scaled): Kh = 16 * exp(-C / ((max+1e-8)*0.1)) ----------------
__global__ void expk_kernel() {
    float negK = -10.0f / (__int_as_float(g_cmax_bits) + 1e-8f);
    size_t nvec = (size_t)NN * KK / 4;
    size_t stride = (size_t)gridDim.x * blockDim.x;
    for (size_t t = (size_t)blockIdx.x * blockDim.x + threadIdx.x; t < nvec; t += stride) {
        float4 c = *reinterpret_cast<const float4*>(g_C + t * 4);
        __half2 h0 = __floats2half2_rn(__expf(c.x * negK) * HSCALE,
                                       __expf(c.y * negK) * HSCALE);
        __half2 h1 = __floats2half2_rn(__expf(c.z * negK) * HSCALE,
                                       __expf(c.w * negK) * HSCALE);
        uint2 pk;
        pk.x = *reinterpret_cast<unsigned*>(&h0);
        pk.y = *reinterpret_cast<unsigned*>(&h1);
        *reinterpret_cast<uint2*>(g_Kh + t * 4) = pk;
    }
}

// ---------------- fused u-step + column-sum: one pass over Kh per iteration ----------------
#define RPW 8
#define ROWS_PER_BLOCK (8 * RPW)   // 64 -> 256 blocks
__global__ __launch_bounds__(256)
void fused_uv_kernel() {
    const int tid = threadIdx.x;
    const int lane = tid & 31;
    const int wid  = tid >> 5;
    const int rowbase = blockIdx.x * ROWS_PER_BLOCK + wid * RPW;

    float vr[32];
#pragma unroll
    for (int q = 0; q < 4; q++) {
        int e = (lane + 32 * q) * 8;
        float4 a = *reinterpret_cast<const float4*>(g_v + e);
        float4 b = *reinterpret_cast<const float4*>(g_v + e + 4);
        vr[q * 8 + 0] = a.x; vr[q * 8 + 1] = a.y; vr[q * 8 + 2] = a.z; vr[q * 8 + 3] = a.w;
        vr[q * 8 + 4] = b.x; vr[q * 8 + 5] = b.y; vr[q * 8 + 6] = b.z; vr[q * 8 + 7] = b.w;
    }
    float colacc[32];
#pragma unroll
    for (int j = 0; j < 32; j++) colacc[j] = 0.0f;

    for (int r = 0; r < RPW; r++) {
        const int row = rowbase + r;
        const __half* rp = g_Kh + (size_t)row * KK;
        float kh[32];
#pragma unroll
        for (int q = 0; q < 4; q++) {
            int e = (lane + 32 * q) * 8;
            int4 raw = *reinterpret_cast<const int4*>(rp + e);
            float2 f;
            f = h2f2((unsigned)raw.x); kh[q * 8 + 0] = f.x; kh[q * 8 + 1] = f.y;
            f = h2f2((unsigned)raw.y); kh[q * 8 + 2] = f.x; kh[q * 8 + 3] = f.y;
            f = h2f2((unsigned)raw.z); kh[q * 8 + 4] = f.x; kh[q * 8 + 5] = f.y;
            f = h2f2((unsigned)raw.w); kh[q * 8 + 6] = f.x; kh[q * 8 + 7] = f.y;
        }
        float dot = 0.0f;
#pragma unroll
        for (int j = 0; j < 32; j++) dot = fmaf(kh[j], vr[j], dot);
#pragma unroll
        for (int o = 16; o; o >>= 1) dot += __shfl_xor_sync(0xffffffffu, dot, o);
        float u = MU_F / (dot * INV_HSCALE + 1e-8f);
        if (!lane) g_u[row] = u;
#pragma unroll
        for (int j = 0; j < 32; j++) colacc[j] = fmaf(u, kh[j], colacc[j]);
    }

    __shared__ float sm[8][KK];
#pragma unroll
    for (int q = 0; q < 4; q++) {
        int e = (lane + 32 * q) * 8;
        *reinterpret_cast<float4*>(&sm[wid][e]) =
            make_float4(colacc[q * 8 + 0], colacc[q * 8 + 1], colacc[q * 8 + 2], colacc[q * 8 + 3]);
        *reinterpret_cast<float4*>(&sm[wid][e + 4]) =
            make_float4(colacc[q * 8 + 4], colacc[q * 8 + 5], colacc[q * 8 + 6], colacc[q * 8 + 7]);
    }
    __syncthreads();
#pragma unroll
    for (int c = 0; c < 4; c++) {
        int col = tid + c * 256;
        float s = sm[0][col];
#pragma unroll
        for (int w = 1; w < 8; w++) s += sm[w][col];
        atomicAdd(&g_s[col], s);
    }
}

// ---------------- v-step: v_j = nu / (s_j / 16 + 1e-8); re-zero s ----------------
__global__ void v_kernel() {
    int j = blockIdx.x * 256 + threadIdx.x;
    if (j < KK) {
        g_v[j] = NU_F / (g_s[j] * INV_HSCALE + 1e-8f);
        g_s[j] = 0.0f;
    }
}

// ---------------- final: T = u * exp(-Cn/eps) * v, loss = sum(T * Cn) ----------------
__global__ __launch_bounds__(256)
void final_kernel(float* __restrict__ out) {
    float invM = 1.0f / (__int_as_float(g_cmax_bits) + 1e-8f);
    size_t nvec = (size_t)NN * KK / 4;
    size_t stride = (size_t)gridDim.x * blockDim.x;
    float lsum = 0.f;
    for (size_t t = (size_t)blockIdx.x * blockDim.x + threadIdx.x; t < nvec; t += stride) {
        size_t base = t * 4;
        int i = (int)(base >> 10);
        int j = (int)(base & 1023);
        float4 c = *reinterpret_cast<const float4*>(g_C + base);
        float4 vj = *reinterpret_cast<const float4*>(g_v + j);
        float ui = g_u[i];
        float cn0 = c.x * invM, cn1 = c.y * invM, cn2 = c.z * invM, cn3 = c.w * invM;
        float t0 = ui * __expf(-cn0 * 10.0f) * vj.x;
        float t1 = ui * __expf(-cn1 * 10.0f) * vj.y;
        float t2 = ui * __expf(-cn2 * 10.0f) * vj.z;
        float t3 = ui * __expf(-cn3 * 10.0f) * vj.w;
        *reinterpret_cast<float4*>(out + base) = make_float4(t0, t1, t2, t3);
        lsum += t0 * cn0 + t1 * cn1 + t2 * cn2 + t3 * cn3;
    }
#pragma unroll
    for (int o = 16; o; o >>= 1) lsum += __shfl_xor_sync(0xffffffffu, lsum, o);
    __shared__ float ws[8];
    int lane = threadIdx.x & 31, wid = threadIdx.x >> 5;
    if (!lane) ws[wid] = lsum;
    __syncthreads();
    if (threadIdx.x == 0) {
        float s = 0.f;
#pragma unroll
        for (int i = 0; i < 8; i++) s += ws[i];
        atomicAdd(out + (size_t)NN * KK, s);
    }
}

// ---------------- launch ----------------
extern "C" void kernel_launch(void* const* d_in, const int* in_sizes, int n_in,
                              void* d_out, int out_size) {
    const float* x = (const float*)d_in[0];   // [16384, 512]
    const float* p = (const float*)d_in[1];   // [1024, 512]
    float* out = (float*)d_out;               // T_star [16384,1024] then loss scalar

    cudaFuncSetAttribute(gemm_mma_kernel,
                         cudaFuncAttributeMaxDynamicSharedMemorySize, GEMM_SMEM);

    init_kernel<<<4, 256>>>(out);
    split_kernel<<<NN, 128>>>(x, 0);
    split_kernel<<<KK, 128>>>(p, 1);
    gemm_mma_kernel<<<dim3(KK / 128, NN / 128), 256, GEMM_SMEM>>>();
    expk_kernel<<<4096, 256>>>();
    for (int it = 0; it < ITERS; it++) {
        fused_uv_kernel<<<NN / ROWS_PER_BLOCK, 256>>>();
        v_kernel<<<4, 256>>>();
    }
    final_kernel<<<2048, 256>>>(out);
}

// round 8
// speedup vs baseline: 1.6874x; 1.1067x over previous
#include <cuda_runtime.h>
#include <cuda_fp16.h>
#include <cstdint>

#define NN 16384
#define KK 1024
#define DD 512
#define ITERS 20
#define HSCALE 16.0f
#define INV_HSCALE (1.0f/16.0f)
#define MU_F (1.0f/16384.0f)
#define NU_F (1.0f/1024.0f)

// ---------------- scratch (static device globals; no runtime allocation) ----------------
__device__ float  g_C[(size_t)NN * KK];        // raw cost matrix (64 MB)
__device__ __half g_Kh[(size_t)NN * KK];       // K_eps * 16 in fp16 (32 MB)
__device__ __half g_xh[(size_t)NN * DD];       // fp16 copy of x
__device__ __half g_ph[(size_t)KK * DD];       // fp16 copy of p
__device__ float  g_u[NN];
__device__ float  g_s[ITERS + 1][KK];          // time-indexed column sums (x16 scaled)
__device__ float  g_dx[NN];
__device__ float  g_dp[KK];
__device__ int    g_cmax_bits;

__device__ __forceinline__ float2 h2f2(unsigned v) {
    __half2 h = *reinterpret_cast<__half2*>(&v);
    return __half22float2(h);
}
__device__ __forceinline__ float v_of_s(float s) {
    return __fdividef(NU_F, s * INV_HSCALE + 1e-8f);
}

__device__ __forceinline__ uint32_t s2u(const void* p) {
    uint32_t r;
    asm("{ .reg .u64 t; cvta.to.shared.u64 t, %1; cvt.u32.u64 %0, t; }" : "=r"(r) : "l"(p));
    return r;
}
__device__ __forceinline__ void cp16u(uint32_t dst, const void* src) {
    asm volatile("cp.async.cg.shared.global [%0], [%1], 16;" :: "r"(dst), "l"(src));
}
__device__ __forceinline__ void ldsm4(unsigned* r, uint32_t a) {
    asm volatile("ldmatrix.sync.aligned.m8n8.x4.shared.b16 {%0,%1,%2,%3}, [%4];"
        : "=r"(r[0]), "=r"(r[1]), "=r"(r[2]), "=r"(r[3]) : "r"(a));
}
__device__ __forceinline__ void mma_f16(float* d, const unsigned* a,
                                        unsigned b0, unsigned b1) {
    asm volatile(
        "mma.sync.aligned.m16n8k16.row.col.f32.f16.f16.f32 "
        "{%0,%1,%2,%3}, {%4,%5,%6,%7}, {%8,%9}, {%0,%1,%2,%3};"
        : "+f"(d[0]), "+f"(d[1]), "+f"(d[2]), "+f"(d[3])
        : "r"(a[0]), "r"(a[1]), "r"(a[2]), "r"(a[3]), "r"(b0), "r"(b1));
}

// ---------------- init: s[0] -> v==1, s[1..20] = 0, cmax = 0, loss slot = 0 ----------------
__global__ void init_kernel(float* __restrict__ out) {
    const float S0 = (NU_F - 1e-8f) * HSCALE;   // makes v_of_s(S0) == 1
    int t = blockIdx.x * 256 + threadIdx.x;
    if (t < (ITERS + 1) * KK)
        (&g_s[0][0])[t] = (t < KK) ? S0 : 0.0f;
    if (t == 0) { g_cmax_bits = 0; out[(size_t)NN * KK] = 0.0f; }
}

// ---------------- convert f32 -> fp16 + row squared norm ----------------
__global__ void split_kernel(const float* __restrict__ src, int which) {
    int row = blockIdx.x;
    int t = threadIdx.x;  // 128 threads, 4 floats each
    float4 v = reinterpret_cast<const float4*>(src + (size_t)row * DD)[t];

    __half2 h0 = __floats2half2_rn(v.x, v.y);
    __half2 h1 = __floats2half2_rn(v.z, v.w);
    __half* dh = which ? g_ph : g_xh;
    uint2 pk;
    pk.x = *reinterpret_cast<unsigned*>(&h0);
    pk.y = *reinterpret_cast<unsigned*>(&h1);
    *reinterpret_cast<uint2*>(dh + (size_t)row * DD + t * 4) = pk;

    float nrm = v.x * v.x + v.y * v.y + v.z * v.z + v.w * v.w;
#pragma unroll
    for (int o = 16; o; o >>= 1) nrm += __shfl_xor_sync(0xffffffffu, nrm, o);
    __shared__ float w[4];
    int lane = t & 31, wid = t >> 5;
    if (!lane) w[wid] = nrm;
    __syncthreads();
    if (t == 0) {
        float s = w[0] + w[1] + w[2] + w[3];
        if (which == 0) g_dx[row] = s; else g_dp[row] = s;
    }
}

// ---------------- HMMA GEMM (single-pass fp16) + cost epilogue ----------------
#define BK 64
#define NCHUNK (DD / BK)          // 8
#define ROWB 144                  // bytes per 64-element fp16 row (128 + 16 pad)
#define PARTB (128 * ROWB)        // 18432
#define STAGEB (2 * PARTB)        // 36864: [A, B]
#define GEMM_SMEM (2 * STAGEB)    // 73728

__device__ __forceinline__ void load_chunk(uint32_t st, int bm, int bn, int k0, int tid) {
#pragma unroll
    for (int part = 0; part < 2; part++) {
        const __half* src = part ? g_ph : g_xh;
        const int rbase = part ? bn : bm;
        uint32_t dst = st + part * PARTB;
#pragma unroll
        for (int i = 0; i < 4; i++) {
            int g = tid + i * 256;          // 1024 granules of 16B per part
            int row = g >> 3, c = g & 7;
            cp16u(dst + row * ROWB + c * 16,
                  src + (size_t)(rbase + row) * DD + k0 + c * 8);
        }
    }
}

__global__ __launch_bounds__(256, 2)
void gemm_mma_kernel() {
    extern __shared__ __align__(16) char smem[];
    __shared__ float dpc[128];
    const uint32_t sb = s2u(smem);
    const int tid = threadIdx.x;
    const int wid = tid >> 5, lane = tid & 31;
    const int g = lane >> 2;
    const int t2 = (lane & 3) * 2;
    const int warpM = wid & 3, warpN = wid >> 2;
    const int bn = blockIdx.x * 128;
    const int bm = blockIdx.y * 128;

    if (tid < 128) dpc[tid] = g_dp[bn + tid];

    const uint32_t aoff = (uint32_t)((warpM * 32 + (lane & 15)) * ROWB + (lane >> 4) * 16);
    const uint32_t boff = (uint32_t)((warpN * 64 + (lane & 15)) * ROWB + (lane >> 4) * 16);

    float d[2][8][4];
#pragma unroll
    for (int mi = 0; mi < 2; mi++)
#pragma unroll
        for (int ni = 0; ni < 8; ni++)
#pragma unroll
            for (int q = 0; q < 4; q++) d[mi][ni][q] = 0.0f;

    load_chunk(sb, bm, bn, 0, tid);
    asm volatile("cp.async.commit_group;");

    for (int s = 0; s < NCHUNK; s++) {
        if (s + 1 < NCHUNK) {
            load_chunk(sb + ((s + 1) & 1) * STAGEB, bm, bn, (s + 1) * BK, tid);
            asm volatile("cp.async.commit_group;");
            asm volatile("cp.async.wait_group 1;");
        } else {
            asm volatile("cp.async.wait_group 0;");
        }
        __syncthreads();

        const uint32_t A = sb + (s & 1) * STAGEB;
        const uint32_t B = A + PARTB;

#pragma unroll
        for (int ks = 0; ks < 4; ks++) {
            unsigned a[2][4], b[4][4];
            ldsm4(a[0], A + aoff + ks * 32);
            ldsm4(a[1], A + aoff + 16 * ROWB + ks * 32);
#pragma unroll
            for (int q = 0; q < 4; q++)
                ldsm4(b[q], B + boff + q * 16 * ROWB + ks * 32);
#pragma unroll
            for (int q = 0; q < 4; q++)
#pragma unroll
                for (int mi = 0; mi < 2; mi++) {
                    mma_f16(d[mi][2 * q],     a[mi], b[q][0], b[q][2]);
                    mma_f16(d[mi][2 * q + 1], a[mi], b[q][1], b[q][3]);
                }
        }
        __syncthreads();
    }

    float tmax = 0.0f;
#pragma unroll
    for (int mi = 0; mi < 2; mi++) {
#pragma unroll
        for (int h = 0; h < 2; h++) {
            int row = bm + warpM * 32 + mi * 16 + h * 8 + g;
            float dxr = g_dx[row];
            float* cp = g_C + (size_t)row * KK + bn + warpN * 64;
#pragma unroll
            for (int ni = 0; ni < 8; ni++) {
                int c0 = ni * 8 + t2;
                float o0 = dxr + dpc[warpN * 64 + c0]     - 2.0f * d[mi][ni][h * 2];
                float o1 = dxr + dpc[warpN * 64 + c0 + 1] - 2.0f * d[mi][ni][h * 2 + 1];
                tmax = fmaxf(tmax, fmaxf(o0, o1));
                *reinterpret_cast<float2*>(cp + c0) = make_float2(o0, o1);
            }
        }
    }
#pragma unroll
    for (int o = 16; o; o >>= 1)
        tmax = fmaxf(tmax, __shfl_xor_sync(0xffffffffu, tmax, o));
    if (!lane) atomicMax(&g_cmax_bits, __float_as_int(tmax));
}

// ---------------- K_eps (fp16, x16 scaled): Kh = 16 * exp(-C / ((max+1e-8)*0.1)) ----------------
__global__ void expk_kernel() {
    float negK = -10.0f / (__int_as_float(g_cmax_bits) + 1e-8f);
    size_t nvec = (size_t)NN * KK / 4;
    size_t stride = (size_t)gridDim.x * blockDim.x;
    for (size_t t = (size_t)blockIdx.x * blockDim.x + threadIdx.x; t < nvec; t += stride) {
        float4 c = *reinterpret_cast<const float4*>(g_C + t * 4);
        __half2 h0 = __floats2half2_rn(__expf(c.x * negK) * HSCALE,
                                       __expf(c.y * negK) * HSCALE);
        __half2 h1 = __floats2half2_rn(__expf(c.z * negK) * HSCALE,
                                       __expf(c.w * negK) * HSCALE);
        uint2 pk;
        pk.x = *reinterpret_cast<unsigned*>(&h0);
        pk.y = *reinterpret_cast<unsigned*>(&h1);
        *reinterpret_cast<uint2*>(g_Kh + t * 4) = pk;
    }
}

// ---------------- fused iteration: v(from s[it]) inline, u-step, col-sums -> s[it+1] ----------------
// 256 threads = 8 warps, 8 rows/warp processed in PAIRS (two overlapping latency chains).
// Lane owns 32 fixed columns: (lane + 32q)*8 + i. Kh kept as raw u32, converted twice.
#define RPW 8
#define ROWS_PER_BLOCK (8 * RPW)   // 64 -> 256 blocks (all co-resident at 2 blocks/SM)
__global__ __launch_bounds__(256, 2)
void fused_uv_kernel(int it) {
    const int tid = threadIdx.x;
    const int lane = tid & 31;
    const int wid  = tid >> 5;
    const int rowbase = blockIdx.x * ROWS_PER_BLOCK + wid * RPW;
    const float* __restrict__ sprev = g_s[it];
    float* __restrict__ snext = g_s[it + 1];

    // v for this lane's 32 columns, computed inline from s[it]
    float vr[32];
#pragma unroll
    for (int q = 0; q < 4; q++) {
        int e = (lane + 32 * q) * 8;
        float4 a = *reinterpret_cast<const float4*>(sprev + e);
        float4 b = *reinterpret_cast<const float4*>(sprev + e + 4);
        vr[q * 8 + 0] = v_of_s(a.x); vr[q * 8 + 1] = v_of_s(a.y);
        vr[q * 8 + 2] = v_of_s(a.z); vr[q * 8 + 3] = v_of_s(a.w);
        vr[q * 8 + 4] = v_of_s(b.x); vr[q * 8 + 5] = v_of_s(b.y);
        vr[q * 8 + 6] = v_of_s(b.z); vr[q * 8 + 7] = v_of_s(b.w);
    }
    float colacc[32];
#pragma unroll
    for (int j = 0; j < 32; j++) colacc[j] = 0.0f;

#pragma unroll
    for (int pr = 0; pr < RPW / 2; pr++) {
        const int r0 = rowbase + 2 * pr;
        const __half* p0 = g_Kh + (size_t)r0 * KK;
        const __half* p1 = p0 + KK;
        uint4 raw0[4], raw1[4];
#pragma unroll
        for (int q = 0; q < 4; q++) {
            int e = (lane + 32 * q) * 8;
            raw0[q] = *reinterpret_cast<const uint4*>(p0 + e);
            raw1[q] = *reinterpret_cast<const uint4*>(p1 + e);
        }
        // dots with 4 accumulators each, two independent chains
        float a0 = 0.f, b0 = 0.f, c0 = 0.f, d0 = 0.f;
        float a1 = 0.f, b1 = 0.f, c1 = 0.f, d1 = 0.f;
#pragma unroll
        for (int q = 0; q < 4; q++) {
            float2 f;
            f = h2f2(raw0[q].x); a0 = fmaf(f.x, vr[q*8+0], a0); b0 = fmaf(f.y, vr[q*8+1], b0);
            f = h2f2(raw0[q].y); c0 = fmaf(f.x, vr[q*8+2], c0); d0 = fmaf(f.y, vr[q*8+3], d0);
            f = h2f2(raw0[q].z); a0 = fmaf(f.x, vr[q*8+4], a0); b0 = fmaf(f.y, vr[q*8+5], b0);
            f = h2f2(raw0[q].w); c0 = fmaf(f.x, vr[q*8+6], c0); d0 = fmaf(f.y, vr[q*8+7], d0);
            f = h2f2(raw1[q].x); a1 = fmaf(f.x, vr[q*8+0], a1); b1 = fmaf(f.y, vr[q*8+1], b1);
            f = h2f2(raw1[q].y); c1 = fmaf(f.x, vr[q*8+2], c1); d1 = fmaf(f.y, vr[q*8+3], d1);
            f = h2f2(raw1[q].z); a1 = fmaf(f.x, vr[q*8+4], a1); b1 = fmaf(f.y, vr[q*8+5], b1);
            f = h2f2(raw1[q].w); c1 = fmaf(f.x, vr[q*8+6], c1); d1 = fmaf(f.y, vr[q*8+7], d1);
        }
        float dot0 = (a0 + b0) + (c0 + d0);
        float dot1 = (a1 + b1) + (c1 + d1);
#pragma unroll
        for (int o = 16; o; o >>= 1) {
            dot0 += __shfl_xor_sync(0xffffffffu, dot0, o);
            dot1 += __shfl_xor_sync(0xffffffffu, dot1, o);
        }
        float u0 = __fdividef(MU_F, dot0 * INV_HSCALE + 1e-8f);
        float u1 = __fdividef(MU_F, dot1 * INV_HSCALE + 1e-8f);
        if (!lane) {
            g_u[r0] = u0;
            g_u[r0 + 1] = u1;
        }
#pragma unroll
        for (int q = 0; q < 4; q++) {
            float2 f;
            f = h2f2(raw0[q].x); colacc[q*8+0] = fmaf(u0, f.x, colacc[q*8+0]); colacc[q*8+1] = fmaf(u0, f.y, colacc[q*8+1]);
            f = h2f2(raw0[q].y); colacc[q*8+2] = fmaf(u0, f.x, colacc[q*8+2]); colacc[q*8+3] = fmaf(u0, f.y, colacc[q*8+3]);
            f = h2f2(raw0[q].z); colacc[q*8+4] = fmaf(u0, f.x, colacc[q*8+4]); colacc[q*8+5] = fmaf(u0, f.y, colacc[q*8+5]);
            f = h2f2(raw0[q].w); colacc[q*8+6] = fmaf(u0, f.x, colacc[q*8+6]); colacc[q*8+7] = fmaf(u0, f.y, colacc[q*8+7]);
            f = h2f2(raw1[q].x); colacc[q*8+0] = fmaf(u1, f.x, colacc[q*8+0]); colacc[q*8+1] = fmaf(u1, f.y, colacc[q*8+1]);
            f = h2f2(raw1[q].y); colacc[q*8+2] = fmaf(u1, f.x, colacc[q*8+2]); colacc[q*8+3] = fmaf(u1, f.y, colacc[q*8+3]);
            f = h2f2(raw1[q].z); colacc[q*8+4] = fmaf(u1, f.x, colacc[q*8+4]); colacc[q*8+5] = fmaf(u1, f.y, colacc[q*8+5]);
            f = h2f2(raw1[q].w); colacc[q*8+6] = fmaf(u1, f.x, colacc[q*8+6]); colacc[q*8+7] = fmaf(u1, f.y, colacc[q*8+7]);
        }
    }

    // block-level reduction of column partials, then one atomicAdd per column per block
    __shared__ float sm[8][KK];
#pragma unroll
    for (int q = 0; q < 4; q++) {
        int e = (lane + 32 * q) * 8;
        *reinterpret_cast<float4*>(&sm[wid][e]) =
            make_float4(colacc[q*8+0], colacc[q*8+1], colacc[q*8+2], colacc[q*8+3]);
        *reinterpret_cast<float4*>(&sm[wid][e + 4]) =
            make_float4(colacc[q*8+4], colacc[q*8+5], colacc[q*8+6], colacc[q*8+7]);
    }
    __syncthreads();
#pragma unroll
    for (int c = 0; c < 4; c++) {
        int col = tid + c * 256;
        float s = sm[0][col];
#pragma unroll
        for (int w = 1; w < 8; w++) s += sm[w][col];
        atomicAdd(&snext[col], s);
    }
}

// ---------------- final: T = u * exp(-Cn/eps) * v(s[20]), loss = sum(T * Cn) ----------------
__global__ __launch_bounds__(256)
void final_kernel(float* __restrict__ out) {
    float invM = 1.0f / (__int_as_float(g_cmax_bits) + 1e-8f);
    const float* __restrict__ slast = g_s[ITERS];
    size_t nvec = (size_t)NN * KK / 4;
    size_t stride = (size_t)gridDim.x * blockDim.x;
    float lsum = 0.f;
    for (size_t t = (size_t)blockIdx.x * blockDim.x + threadIdx.x; t < nvec; t += stride) {
        size_t base = t * 4;
        int i = (int)(base >> 10);
        int j = (int)(base & 1023);
        float4 c = *reinterpret_cast<const float4*>(g_C + base);
        float4 sj = *reinterpret_cast<const float4*>(slast + j);
        float ui = g_u[i];
        float cn0 = c.x * invM, cn1 = c.y * invM, cn2 = c.z * invM, cn3 = c.w * invM;
        float t0 = ui * __expf(-cn0 * 10.0f) * v_of_s(sj.x);
        float t1 = ui * __expf(-cn1 * 10.0f) * v_of_s(sj.y);
        float t2 = ui * __expf(-cn2 * 10.0f) * v_of_s(sj.z);
        float t3 = ui * __expf(-cn3 * 10.0f) * v_of_s(sj.w);
        *reinterpret_cast<float4*>(out + base) = make_float4(t0, t1, t2, t3);
        lsum += t0 * cn0 + t1 * cn1 + t2 * cn2 + t3 * cn3;
    }
#pragma unroll
    for (int o = 16; o; o >>= 1) lsum += __shfl_xor_sync(0xffffffffu, lsum, o);
    __shared__ float ws[8];
    int lane = threadIdx.x & 31, wid = threadIdx.x >> 5;
    if (!lane) ws[wid] = lsum;
    __syncthreads();
    if (threadIdx.x == 0) {
        float s = 0.f;
#pragma unroll
        for (int i = 0; i < 8; i++) s += ws[i];
        atomicAdd(out + (size_t)NN * KK, s);
    }
}

// ---------------- launch ----------------
extern "C" void kernel_launch(void* const* d_in, const int* in_sizes, int n_in,
                              void* d_out, int out_size) {
    const float* x = (const float*)d_in[0];   // [16384, 512]
    const float* p = (const float*)d_in[1];   // [1024, 512]
    float* out = (float*)d_out;               // T_star [16384,1024] then loss scalar

    cudaFuncSetAttribute(gemm_mma_kernel,
                         cudaFuncAttributeMaxDynamicSharedMemorySize, GEMM_SMEM);

    init_kernel<<<(((ITERS + 1) * KK) + 255) / 256, 256>>>(out);
    split_kernel<<<NN, 128>>>(x, 0);
    split_kernel<<<KK, 128>>>(p, 1);
    gemm_mma_kernel<<<dim3(KK / 128, NN / 128), 256, GEMM_SMEM>>>();
    expk_kernel<<<4096, 256>>>();
    for (int it = 0; it < ITERS; it++)
        fused_uv_kernel<<<NN / ROWS_PER_BLOCK, 256>>>(it);
    final_kernel<<<2048, 256>>>(out);
}

// round 9
// speedup vs baseline: 1.6948x; 1.0044x over previous
#include <cuda_runtime.h>
#include <cuda_fp16.h>
#include <cstdint>

#define NN 16384
#define KK 1024
#define DD 512
#define ITERS 20
#define HSCALE 16.0f
#define INV_HSCALE (1.0f/16.0f)
#define MU_F (1.0f/16384.0f)
#define NU_F (1.0f/1024.0f)
#define USCALE 1024.0f
#define S_DIV (INV_HSCALE / USCALE)     // s_stored * S_DIV = true (K^T u) sum

// ---------------- scratch (static device globals; no runtime allocation) ----------------
__device__ float  g_C[(size_t)NN * KK];        // raw cost matrix (64 MB)
__device__ __half g_Kh[(size_t)NN * KK];       // K_eps * 16 in fp16 (32 MB)
__device__ __half g_xh[(size_t)NN * DD];       // fp16 copy of x
__device__ __half g_ph[(size_t)KK * DD];       // fp16 copy of p
__device__ float  g_u[NN];
__device__ float  g_s[ITERS + 1][KK];          // time-indexed column sums (x16*1024 scaled)
__device__ float  g_dx[NN];
__device__ float  g_dp[KK];
__device__ int    g_cmax_bits;

__device__ __forceinline__ float2 h2f2(unsigned v) {
    __half2 h = *reinterpret_cast<__half2*>(&v);
    return __half22float2(h);
}
__device__ __forceinline__ float v_of_s(float s) {
    return __fdividef(NU_F, s * S_DIV + 1e-8f);
}

// ---- packed f32x2 helpers (Blackwell FFMA2) ----
__device__ __forceinline__ unsigned long long pack2(float lo, float hi) {
    unsigned long long r;
    asm("mov.b64 %0, {%1, %2};" : "=l"(r) : "f"(lo), "f"(hi));
    return r;
}
__device__ __forceinline__ void fma2(unsigned long long& d,
                                     unsigned long long a,
                                     unsigned long long b) {
    asm("fma.rn.f32x2 %0, %1, %2, %0;" : "+l"(d) : "l"(a), "l"(b));
}
__device__ __forceinline__ float2 unpack2(unsigned long long v) {
    float lo, hi;
    asm("mov.b64 {%0, %1}, %2;" : "=f"(lo), "=f"(hi) : "l"(v));
    return make_float2(lo, hi);
}
// half2 (as u32) -> packed f32x2 (as u64)
__device__ __forceinline__ unsigned long long h2tof2(unsigned h) {
    unsigned long long r;
    asm("{.reg .b16 l, h;\n\t"
        ".reg .f32 fl, fh;\n\t"
        "mov.b32 {l, h}, %1;\n\t"
        "cvt.f32.f16 fl, l;\n\t"
        "cvt.f32.f16 fh, h;\n\t"
        "mov.b64 %0, {fl, fh};}" : "=l"(r) : "r"(h));
    return r;
}
__device__ __forceinline__ __half2 u32h2(unsigned v) {
    return *reinterpret_cast<__half2*>(&v);
}

__device__ __forceinline__ uint32_t s2u(const void* p) {
    uint32_t r;
    asm("{ .reg .u64 t; cvta.to.shared.u64 t, %1; cvt.u32.u64 %0, t; }" : "=r"(r) : "l"(p));
    return r;
}
__device__ __forceinline__ void cp16u(uint32_t dst, const void* src) {
    asm volatile("cp.async.cg.shared.global [%0], [%1], 16;" :: "r"(dst), "l"(src));
}
__device__ __forceinline__ void ldsm4(unsigned* r, uint32_t a) {
    asm volatile("ldmatrix.sync.aligned.m8n8.x4.shared.b16 {%0,%1,%2,%3}, [%4];"
        : "=r"(r[0]), "=r"(r[1]), "=r"(r[2]), "=r"(r[3]) : "r"(a));
}
__device__ __forceinline__ void mma_f16(float* d, const unsigned* a,
                                        unsigned b0, unsigned b1) {
    asm volatile(
        "mma.sync.aligned.m16n8k16.row.col.f32.f16.f16.f32 "
        "{%0,%1,%2,%3}, {%4,%5,%6,%7}, {%8,%9}, {%0,%1,%2,%3};"
        : "+f"(d[0]), "+f"(d[1]), "+f"(d[2]), "+f"(d[3])
        : "r"(a[0]), "r"(a[1]), "r"(a[2]), "r"(a[3]), "r"(b0), "r"(b1));
}

// ---------------- init: s[0] -> v==1, s[1..20] = 0, cmax = 0, loss slot = 0 ----------------
__global__ void init_kernel(float* __restrict__ out) {
    const float S0 = (NU_F - 1e-8f) / S_DIV;   // makes v_of_s(S0) == 1
    int t = blockIdx.x * 256 + threadIdx.x;
    if (t < (ITERS + 1) * KK)
        (&g_s[0][0])[t] = (t < KK) ? S0 : 0.0f;
    if (t == 0) { g_cmax_bits = 0; out[(size_t)NN * KK] = 0.0f; }
}

// ---------------- convert f32 -> fp16 + row squared norm ----------------
__global__ void split_kernel(const float* __restrict__ src, int which) {
    int row = blockIdx.x;
    int t = threadIdx.x;  // 128 threads, 4 floats each
    float4 v = reinterpret_cast<const float4*>(src + (size_t)row * DD)[t];

    __half2 h0 = __floats2half2_rn(v.x, v.y);
    __half2 h1 = __floats2half2_rn(v.z, v.w);
    __half* dh = which ? g_ph : g_xh;
    uint2 pk;
    pk.x = *reinterpret_cast<unsigned*>(&h0);
    pk.y = *reinterpret_cast<unsigned*>(&h1);
    *reinterpret_cast<uint2*>(dh + (size_t)row * DD + t * 4) = pk;

    float nrm = v.x * v.x + v.y * v.y + v.z * v.z + v.w * v.w;
#pragma unroll
    for (int o = 16; o; o >>= 1) nrm += __shfl_xor_sync(0xffffffffu, nrm, o);
    __shared__ float w[4];
    int lane = t & 31, wid = t >> 5;
    if (!lane) w[wid] = nrm;
    __syncthreads();
    if (t == 0) {
        float s = w[0] + w[1] + w[2] + w[3];
        if (which == 0) g_dx[row] = s; else g_dp[row] = s;
    }
}

// ---------------- HMMA GEMM (single-pass fp16) + cost epilogue ----------------
#define BK 64
#define NCHUNK (DD / BK)          // 8
#define ROWB 144                  // bytes per 64-element fp16 row (128 + 16 pad)
#define PARTB (128 * ROWB)        // 18432
#define STAGEB (2 * PARTB)        // 36864: [A, B]
#define GEMM_SMEM (2 * STAGEB)    // 73728

__device__ __forceinline__ void load_chunk(uint32_t st, int bm, int bn, int k0, int tid) {
#pragma unroll
    for (int part = 0; part < 2; part++) {
        const __half* src = part ? g_ph : g_xh;
        const int rbase = part ? bn : bm;
        uint32_t dst = st + part * PARTB;
#pragma unroll
        for (int i = 0; i < 4; i++) {
            int g = tid + i * 256;
            int row = g >> 3, c = g & 7;
            cp16u(dst + row * ROWB + c * 16,
                  src + (size_t)(rbase + row) * DD + k0 + c * 8);
        }
    }
}

__global__ __launch_bounds__(256, 2)
void gemm_mma_kernel() {
    extern __shared__ __align__(16) char smem[];
    __shared__ float dpc[128];
    const uint32_t sb = s2u(smem);
    const int tid = threadIdx.x;
    const int wid = tid >> 5, lane = tid & 31;
    const int g = lane >> 2;
    const int t2 = (lane & 3) * 2;
    const int warpM = wid & 3, warpN = wid >> 2;
    const int bn = blockIdx.x * 128;
    const int bm = blockIdx.y * 128;

    if (tid < 128) dpc[tid] = g_dp[bn + tid];

    const uint32_t aoff = (uint32_t)((warpM * 32 + (lane & 15)) * ROWB + (lane >> 4) * 16);
    const uint32_t boff = (uint32_t)((warpN * 64 + (lane & 15)) * ROWB + (lane >> 4) * 16);

    float d[2][8][4];
#pragma unroll
    for (int mi = 0; mi < 2; mi++)
#pragma unroll
        for (int ni = 0; ni < 8; ni++)
#pragma unroll
            for (int q = 0; q < 4; q++) d[mi][ni][q] = 0.0f;

    load_chunk(sb, bm, bn, 0, tid);
    asm volatile("cp.async.commit_group;");

    for (int s = 0; s < NCHUNK; s++) {
        if (s + 1 < NCHUNK) {
            load_chunk(sb + ((s + 1) & 1) * STAGEB, bm, bn, (s + 1) * BK, tid);
            asm volatile("cp.async.commit_group;");
            asm volatile("cp.async.wait_group 1;");
        } else {
            asm volatile("cp.async.wait_group 0;");
        }
        __syncthreads();

        const uint32_t A = sb + (s & 1) * STAGEB;
        const uint32_t B = A + PARTB;

#pragma unroll
        for (int ks = 0; ks < 4; ks++) {
            unsigned a[2][4], b[4][4];
            ldsm4(a[0], A + aoff + ks * 32);
            ldsm4(a[1], A + aoff + 16 * ROWB + ks * 32);
#pragma unroll
            for (int q = 0; q < 4; q++)
                ldsm4(b[q], B + boff + q * 16 * ROWB + ks * 32);
#pragma unroll
            for (int q = 0; q < 4; q++)
#pragma unroll
                for (int mi = 0; mi < 2; mi++) {
                    mma_f16(d[mi][2 * q],     a[mi], b[q][0], b[q][2]);
                    mma_f16(d[mi][2 * q + 1], a[mi], b[q][1], b[q][3]);
                }
        }
        __syncthreads();
    }

    float tmax = 0.0f;
#pragma unroll
    for (int mi = 0; mi < 2; mi++) {
#pragma unroll
        for (int h = 0; h < 2; h++) {
            int row = bm + warpM * 32 + mi * 16 + h * 8 + g;
            float dxr = g_dx[row];
            float* cp = g_C + (size_t)row * KK + bn + warpN * 64;
#pragma unroll
            for (int ni = 0; ni < 8; ni++) {
                int c0 = ni * 8 + t2;
                float o0 = dxr + dpc[warpN * 64 + c0]     - 2.0f * d[mi][ni][h * 2];
                float o1 = dxr + dpc[warpN * 64 + c0 + 1] - 2.0f * d[mi][ni][h * 2 + 1];
                tmax = fmaxf(tmax, fmaxf(o0, o1));
                *reinterpret_cast<float2*>(cp + c0) = make_float2(o0, o1);
            }
        }
    }
#pragma unroll
    for (int o = 16; o; o >>= 1)
        tmax = fmaxf(tmax, __shfl_xor_sync(0xffffffffu, tmax, o));
    if (!lane) atomicMax(&g_cmax_bits, __float_as_int(tmax));
}

// ---------------- K_eps (fp16, x16 scaled): Kh = 16 * exp(-C / ((max+1e-8)*0.1)) ----------------
__global__ void expk_kernel() {
    float negK = -10.0f / (__int_as_float(g_cmax_bits) + 1e-8f);
    size_t nvec = (size_t)NN * KK / 4;
    size_t stride = (size_t)gridDim.x * blockDim.x;
    for (size_t t = (size_t)blockIdx.x * blockDim.x + threadIdx.x; t < nvec; t += stride) {
        float4 c = *reinterpret_cast<const float4*>(g_C + t * 4);
        __half2 h0 = __floats2half2_rn(__expf(c.x * negK) * HSCALE,
                                       __expf(c.y * negK) * HSCALE);
        __half2 h1 = __floats2half2_rn(__expf(c.z * negK) * HSCALE,
                                       __expf(c.w * negK) * HSCALE);
        uint2 pk;
        pk.x = *reinterpret_cast<unsigned*>(&h0);
        pk.y = *reinterpret_cast<unsigned*>(&h1);
        *reinterpret_cast<uint2*>(g_Kh + t * 4) = pk;
    }
}

// ---------------- fused iteration: v(s[it]) inline, u-step (f32x2 dot), colacc (HFMA2) ----------------
// 8 warps, 8 rows/warp in pairs. Lane owns 32 fixed columns (lane + 32q)*8 + i.
// dot: packed f32x2 FMAs against pre-packed v. colacc: HFMA2 on raw half2 with u*USCALE.
#define RPW 8
#define ROWS_PER_BLOCK (8 * RPW)   // 64 -> 256 blocks
__global__ __launch_bounds__(256, 2)
void fused_uv_kernel(int it) {
    const int tid = threadIdx.x;
    const int lane = tid & 31;
    const int wid  = tid >> 5;
    const int rowbase = blockIdx.x * ROWS_PER_BLOCK + wid * RPW;
    const float* __restrict__ sprev = g_s[it];
    float* __restrict__ snext = g_s[it + 1];

    // v packed as f32x2 pairs matching half2 load layout
    unsigned long long vrp[16];
#pragma unroll
    for (int q = 0; q < 4; q++) {
        int e = (lane + 32 * q) * 8;
        float4 a = *reinterpret_cast<const float4*>(sprev + e);
        float4 b = *reinterpret_cast<const float4*>(sprev + e + 4);
        vrp[4 * q + 0] = pack2(v_of_s(a.x), v_of_s(a.y));
        vrp[4 * q + 1] = pack2(v_of_s(a.z), v_of_s(a.w));
        vrp[4 * q + 2] = pack2(v_of_s(b.x), v_of_s(b.y));
        vrp[4 * q + 3] = pack2(v_of_s(b.z), v_of_s(b.w));
    }
    __half2 colh[16];
#pragma unroll
    for (int j = 0; j < 16; j++) colh[j] = __half2half2(__float2half(0.0f));

#pragma unroll
    for (int pr = 0; pr < RPW / 2; pr++) {
        const int r0 = rowbase + 2 * pr;
        const __half* p0 = g_Kh + (size_t)r0 * KK;
        const __half* p1 = p0 + KK;
        uint4 raw0[4], raw1[4];
#pragma unroll
        for (int q = 0; q < 4; q++) {
            int e = (lane + 32 * q) * 8;
            raw0[q] = *reinterpret_cast<const uint4*>(p0 + e);
            raw1[q] = *reinterpret_cast<const uint4*>(p1 + e);
        }
        // dot: f32x2 packed FMAs, 2 chains per row
        unsigned long long a0 = 0, b0 = 0, a1 = 0, b1 = 0;
#pragma unroll
        for (int q = 0; q < 4; q++) {
            fma2(a0, h2tof2(raw0[q].x), vrp[4 * q + 0]);
            fma2(b0, h2tof2(raw0[q].y), vrp[4 * q + 1]);
            fma2(a0, h2tof2(raw0[q].z), vrp[4 * q + 2]);
            fma2(b0, h2tof2(raw0[q].w), vrp[4 * q + 3]);
            fma2(a1, h2tof2(raw1[q].x), vrp[4 * q + 0]);
            fma2(b1, h2tof2(raw1[q].y), vrp[4 * q + 1]);
            fma2(a1, h2tof2(raw1[q].z), vrp[4 * q + 2]);
            fma2(b1, h2tof2(raw1[q].w), vrp[4 * q + 3]);
        }
        float2 f0a = unpack2(a0), f0b = unpack2(b0);
        float2 f1a = unpack2(a1), f1b = unpack2(b1);
        float dot0 = (f0a.x + f0a.y) + (f0b.x + f0b.y);
        float dot1 = (f1a.x + f1a.y) + (f1b.x + f1b.y);
#pragma unroll
        for (int o = 16; o; o >>= 1) {
            dot0 += __shfl_xor_sync(0xffffffffu, dot0, o);
            dot1 += __shfl_xor_sync(0xffffffffu, dot1, o);
        }
        float u0 = __fdividef(MU_F, dot0 * INV_HSCALE + 1e-8f);
        float u1 = __fdividef(MU_F, dot1 * INV_HSCALE + 1e-8f);
        if (!lane) {
            g_u[r0] = u0;
            g_u[r0 + 1] = u1;
        }
        // colacc: HFMA2 on raw half2 with scaled u broadcast
        __half2 u0h = __float2half2_rn(u0 * USCALE);
        __half2 u1h = __float2half2_rn(u1 * USCALE);
#pragma unroll
        for (int q = 0; q < 4; q++) {
            colh[4*q+0] = __hfma2(u32h2(raw0[q].x), u0h, colh[4*q+0]);
            colh[4*q+1] = __hfma2(u32h2(raw0[q].y), u0h, colh[4*q+1]);
            colh[4*q+2] = __hfma2(u32h2(raw0[q].z), u0h, colh[4*q+2]);
            colh[4*q+3] = __hfma2(u32h2(raw0[q].w), u0h, colh[4*q+3]);
            colh[4*q+0] = __hfma2(u32h2(raw1[q].x), u1h, colh[4*q+0]);
            colh[4*q+1] = __hfma2(u32h2(raw1[q].y), u1h, colh[4*q+1]);
            colh[4*q+2] = __hfma2(u32h2(raw1[q].z), u1h, colh[4*q+2]);
            colh[4*q+3] = __hfma2(u32h2(raw1[q].w), u1h, colh[4*q+3]);
        }
    }

    // convert half2 partials to f32, block-reduce via smem, one atomic per col per block
    __shared__ float sm[8][KK];
#pragma unroll
    for (int q = 0; q < 4; q++) {
        int e = (lane + 32 * q) * 8;
        float2 c0 = __half22float2(colh[4*q+0]);
        float2 c1 = __half22float2(colh[4*q+1]);
        float2 c2 = __half22float2(colh[4*q+2]);
        float2 c3 = __half22float2(colh[4*q+3]);
        *reinterpret_cast<float4*>(&sm[wid][e])     = make_float4(c0.x, c0.y, c1.x, c1.y);
        *reinterpret_cast<float4*>(&sm[wid][e + 4]) = make_float4(c2.x, c2.y, c3.x, c3.y);
    }
    __syncthreads();
#pragma unroll
    for (int c = 0; c < 4; c++) {
        int col = tid + c * 256;
        float s = sm[0][col];
#pragma unroll
        for (int w = 1; w < 8; w++) s += sm[w][col];
        atomicAdd(&snext[col], s);
    }
}

// ---------------- final: T = u * exp(-Cn/eps) * v(s[20]), loss = sum(T * Cn) ----------------
__global__ __launch_bounds__(256)
void final_kernel(float* __restrict__ out) {
    float invM = 1.0f / (__int_as_float(g_cmax_bits) + 1e-8f);
    const float* __restrict__ slast = g_s[ITERS];
    size_t nvec = (size_t)NN * KK / 4;
    size_t stride = (size_t)gridDim.x * blockDim.x;
    float lsum = 0.f;
    for (size_t t = (size_t)blockIdx.x * blockDim.x + threadIdx.x; t < nvec; t += stride) {
        size_t base = t * 4;
        int i = (int)(base >> 10);
        int j = (int)(base & 1023);
        float4 c = *reinterpret_cast<const float4*>(g_C + base);
        float4 sj = *reinterpret_cast<const float4*>(slast + j);
        float ui = g_u[i];
        float cn0 = c.x * invM, cn1 = c.y * invM, cn2 = c.z * invM, cn3 = c.w * invM;
        float t0 = ui * __expf(-cn0 * 10.0f) * v_of_s(sj.x);
        float t1 = ui * __expf(-cn1 * 10.0f) * v_of_s(sj.y);
        float t2 = ui * __expf(-cn2 * 10.0f) * v_of_s(sj.z);
        float t3 = ui * __expf(-cn3 * 10.0f) * v_of_s(sj.w);
        *reinterpret_cast<float4*>(out + base) = make_float4(t0, t1, t2, t3);
        lsum += t0 * cn0 + t1 * cn1 + t2 * cn2 + t3 * cn3;
    }
#pragma unroll
    for (int o = 16; o; o >>= 1) lsum += __shfl_xor_sync(0xffffffffu, lsum, o);
    __shared__ float ws[8];
    int lane = threadIdx.x & 31, wid = threadIdx.x >> 5;
    if (!lane) ws[wid] = lsum;
    __syncthreads();
    if (threadIdx.x == 0) {
        float s = 0.f;
#pragma unroll
        for (int i = 0; i < 8; i++) s += ws[i];
        atomicAdd(out + (size_t)NN * KK, s);
    }
}

// ---------------- launch ----------------
extern "C" void kernel_launch(void* const* d_in, const int* in_sizes, int n_in,
                              void* d_out, int out_size) {
    const float* x = (const float*)d_in[0];   // [16384, 512]
    const float* p = (const float*)d_in[1];   // [1024, 512]
    float* out = (float*)d_out;               // T_star [16384,1024] then loss scalar

    cudaFuncSetAttribute(gemm_mma_kernel,
                         cudaFuncAttributeMaxDynamicSharedMemorySize, GEMM_SMEM);

    init_kernel<<<(((ITERS + 1) * KK) + 255) / 256, 256>>>(out);
    split_kernel<<<NN, 128>>>(x, 0);
    split_kernel<<<KK, 128>>>(p, 1);
    gemm_mma_kernel<<<dim3(KK / 128, NN / 128), 256, GEMM_SMEM>>>();
    expk_kernel<<<4096, 256>>>();
    for (int it = 0; it < ITERS; it++)
        fused_uv_kernel<<<NN / ROWS_PER_BLOCK, 256>>>(it);
    final_kernel<<<2048, 256>>>(out);
}